// round 7
// baseline (speedup 1.0000x reference)
#include <cuda_runtime.h>
#include <cuda_bf16.h>
#include <math.h>
#include <stdint.h>

#define BB 256
#define SS 512
#define RR 128
#define HH 512
#define TT 96
#define GG 2048   // 4*H
#define K2 1024   // 2*H

// ---------------- device scratch ----------------
__device__ __nv_bfloat16 g_hsb[(size_t)SS * BB * HH];   // encoder hidden states bf16 [s][b][h]
__device__ float g_hbuf[2][BB * HH];                    // ping-pong hidden fp32 (for out proj)
__device__ float g_c[BB * HH];                          // cell state fp32 (decoder)
__device__ __nv_bfloat16 g_hhi[2][BB * HH], g_hlo[2][BB * HH];   // split-bf16 h ping-pong
__device__ __nv_bfloat16 g_ctxhi[BB * HH], g_ctxlo[BB * HH];     // split-bf16 context
__device__ __nv_bfloat16 g_Wenc_hi[GG * HH],  g_Wenc_lo[GG * HH];
__device__ __nv_bfloat16 g_WA_hi[(GG + HH) * HH], g_WA_lo[(GG + HH) * HH]; // [gates_h | At] 2560x512
__device__ __nv_bfloat16 g_Wc_hi[GG * HH], g_Wc_lo[GG * HH];               // ctx half of dec Wih
__device__ float g_gates[BB * GG];                     // cached gates_h (fp32)
__device__ float g_v2[GG], g_u2[GG], g_bd2[GG];
__device__ float g_WkT[HH * HH], g_WqT[HH * HH], g_At[HH * HH];
__device__ float g_bqk[HH];
__device__ float g_q2[BB * HH];

// grid-wide barrier state
__device__ unsigned g_bar_count = 0;
__device__ volatile unsigned g_bar_gen = 0;

// ---------------- helpers ----------------
__device__ __forceinline__ uint32_t smem_u32(const void* p) {
    uint32_t a;
    asm("{ .reg .u64 t; cvta.to.shared.u64 t, %1; cvt.u32.u64 %0, t; }" : "=r"(a) : "l"(p));
    return a;
}
__device__ __forceinline__ void cp16(uint32_t dst, const void* src) {
    asm volatile("cp.async.cg.shared.global [%0], [%1], 16;" :: "r"(dst), "l"(src) : "memory");
}
#define CP_COMMIT() asm volatile("cp.async.commit_group;" ::: "memory")
#define CP_WAIT1()  asm volatile("cp.async.wait_group 1;" ::: "memory")
#define CP_WAIT0()  asm volatile("cp.async.wait_group 0;" ::: "memory")

__device__ __forceinline__ void ldm4(uint32_t* r, uint32_t addr) {
    asm volatile("ldmatrix.sync.aligned.m8n8.x4.shared.b16 {%0,%1,%2,%3}, [%4];"
                 : "=r"(r[0]), "=r"(r[1]), "=r"(r[2]), "=r"(r[3]) : "r"(addr));
}
__device__ __forceinline__ void mma16816(float* c, const uint32_t* a, uint32_t b0, uint32_t b1) {
    asm volatile(
        "mma.sync.aligned.m16n8k16.row.col.f32.bf16.bf16.f32 "
        "{%0,%1,%2,%3}, {%4,%5,%6,%7}, {%8,%9}, {%0,%1,%2,%3};"
        : "+f"(c[0]), "+f"(c[1]), "+f"(c[2]), "+f"(c[3])
        : "r"(a[0]), "r"(a[1]), "r"(a[2]), "r"(a[3]), "r"(b0), "r"(b1));
}

__device__ __forceinline__ void grid_sync(unsigned nct) {
    __syncthreads();
    if (threadIdx.x == 0) {
        __threadfence();
        unsigned gen = g_bar_gen;
        unsigned t = atomicInc(&g_bar_count, nct - 1);
        if (t == nct - 1) {
            g_bar_gen = gen + 1;
        } else {
            while (g_bar_gen == gen) __nanosleep(64);
        }
        __threadfence();
    }
    __syncthreads();
}

// tile geometry
#define T_ROW   144
#define T_SZ    (64 * T_ROW)          // 9216
#define TA_HI   0
#define TA_LO   (1 * T_SZ)
#define TB_HI   (2 * T_SZ)
#define TB_LO   (3 * T_SZ)
#define BUFS    (4 * T_SZ)            // 36864
#define SMEM_BYTES (2 * BUFS)         // 73728

// persistent encoder smem
#define W_TILE  (8 * T_SZ)            // 73728
#define A_OFF   (2 * W_TILE)          // 147456
#define PSMEM   (A_OFF + 4 * T_SZ)    // 184320

// attention phase smem blocking (within SMEM_BYTES)
#define ATT_SUB 16640                 // per-sub block: sc 16384 + sm 32 + sl 32 (padded)

// ================= 16-warp 64x64 chunk MMA =================
__device__ __forceinline__ void chunk_mma_16w(uint32_t abase, uint32_t alo_off,
                                              uint32_t bbase, uint32_t blo_off,
                                              int mrow, int ncol, uint32_t rowsel,
                                              float acc[2][4]) {
#pragma unroll
    for (int kk = 0; kk < 4; ++kk) {
        uint32_t kof = kk * 32;
        uint32_t aaddr = abase + mrow * T_ROW + rowsel + kof;
        uint32_t baddr = bbase + ncol * T_ROW + rowsel + kof;
        uint32_t ahr[4], alr[4], bh[4], bl2[4];
        ldm4(ahr, aaddr);
        ldm4(alr, aaddr + alo_off);
        ldm4(bh, baddr);
        ldm4(bl2, baddr + blo_off);
#pragma unroll
        for (int nt = 0; nt < 2; ++nt) {
            mma16816(acc[nt], ahr, bh[nt], bh[nt + 2]);
            mma16816(acc[nt], alr, bh[nt], bh[nt + 2]);
            mma16816(acc[nt], ahr, bl2[nt], bl2[nt + 2]);
        }
    }
}

// ================= persistent encoder (unchanged from R5) =================
__global__ __launch_bounds__(512) void lstm_enc_persist(const float* __restrict__ enc_inputs) {
    extern __shared__ char smem[];
    uint32_t sb = smem_u32(smem);
    int tid = threadIdx.x;
    int w = tid >> 5, l = tid & 31;
    int n0 = blockIdx.x * 64;
    int m0 = blockIdx.y * 64;
    int mrow = (w & 3) * 16;
    int ncol = (w >> 2) * 16;

    for (int i = tid; i < 4096; i += 512) {
        int c = i >> 9, r = (i >> 3) & 63, cu = i & 7;
        uint32_t d = sb + c * T_SZ + r * T_ROW + cu * 16;
        size_t src = (size_t)(n0 + r) * HH + c * 64 + cu * 8;
        cp16(d, g_Wenc_hi + src);
        cp16(d + W_TILE, g_Wenc_lo + src);
    }
    CP_COMMIT();
    CP_WAIT0();
    __syncthreads();

    int bl_ = tid & 63;
    int q0 = (tid >> 6) * 2;
    int b = m0 + bl_;
    int hbase = n0 >> 2;
    float creg[2] = {0.f, 0.f};
    uint32_t rowsel = (l & 15) * T_ROW + (l >> 4) * 16;

    for (int s = 0; s < SS; ++s) {
        int par = s & 1, op = par ^ 1;
        const __nv_bfloat16* __restrict__ ah = g_hhi[par];
        const __nv_bfloat16* __restrict__ al = g_hlo[par];

        float acc[2][4];
#pragma unroll
        for (int nt = 0; nt < 2; ++nt)
#pragma unroll
            for (int r = 0; r < 4; ++r) acc[nt][r] = 0.f;

        auto issueA = [&](int c) {
            if (c < 8) {
                int c0 = c * 64;
                uint32_t buf = sb + A_OFF + (c & 1) * 2 * T_SZ;
                int r = tid >> 3, cu = tid & 7;
                uint32_t d = buf + r * T_ROW + cu * 16;
                cp16(d, ah + (m0 + r) * HH + c0 + cu * 8);
                cp16(d + T_SZ, al + (m0 + r) * HH + c0 + cu * 8);
            }
            CP_COMMIT();
        };

        issueA(0);
        for (int c = 0; c < 8; ++c) {
            issueA(c + 1);
            CP_WAIT1();
            __syncthreads();
            uint32_t abase = sb + A_OFF + (c & 1) * 2 * T_SZ;
            uint32_t wbase = sb + c * T_SZ;
            chunk_mma_16w(abase, T_SZ, wbase, W_TILE, mrow, ncol, rowsel, acc);
            __syncthreads();
        }

        float* Cs = (float*)(smem + A_OFF);
        {
            int g = l >> 2, cc = l & 3;
#pragma unroll
            for (int nt = 0; nt < 2; ++nt) {
                int col = ncol + nt * 8 + cc * 2;
                int r0 = mrow + g, r1 = mrow + g + 8;
                Cs[r0 * 68 + col]     = acc[nt][0];
                Cs[r0 * 68 + col + 1] = acc[nt][1];
                Cs[r1 * 68 + col]     = acc[nt][2];
                Cs[r1 * 68 + col + 1] = acc[nt][3];
            }
        }
        __syncthreads();

        float e = enc_inputs[b * SS + s];
#pragma unroll
        for (int q = 0; q < 2; ++q) {
            int hl = q0 + q;
            int jl = hl * 4;
            int jp = n0 + jl;
            float ri = Cs[bl_ * 68 + jl + 0] + e * g_v2[jp + 0] + g_u2[jp + 0];
            float rf = Cs[bl_ * 68 + jl + 1] + e * g_v2[jp + 1] + g_u2[jp + 1];
            float rg = Cs[bl_ * 68 + jl + 2] + e * g_v2[jp + 2] + g_u2[jp + 2];
            float ro = Cs[bl_ * 68 + jl + 3] + e * g_v2[jp + 3] + g_u2[jp + 3];
            float ig = 1.f / (1.f + expf(-ri));
            float fg = 1.f / (1.f + expf(-rf));
            float gg = tanhf(rg);
            float og = 1.f / (1.f + expf(-ro));
            float cn = fg * creg[q] + ig * gg;
            float hn = og * tanhf(cn);
            creg[q] = cn;
            int idx = b * HH + hbase + hl;
            __nv_bfloat16 hi = __float2bfloat16(hn);
            g_hhi[op][idx] = hi;
            g_hlo[op][idx] = __float2bfloat16(hn - __bfloat162float(hi));
            g_hsb[((size_t)s * BB + b) * HH + hbase + hl] = hi;
            if (s == SS - 1) { g_c[idx] = cn; g_hbuf[op][idx] = hn; }
        }
        grid_sync(128);
    }
}

// ================= persistent decoder: all 96 steps, 4 phases, 128 CTAs x 512 thr =================
__global__ __launch_bounds__(512) void dec_persist(const float* __restrict__ outW,
                                                   const float* __restrict__ outb,
                                                   float* __restrict__ out) {
    extern __shared__ char smem[];
    uint32_t sb = smem_u32(smem);
    int tid = threadIdx.x, cta = blockIdx.x;
    int w = tid >> 5, l = tid & 31;
    int mrow = (w & 3) * 16, ncol = (w >> 2) * 16;
    uint32_t rowsel = (l & 15) * T_ROW + (l >> 4) * 16;
    int g2 = l >> 2, cc = l & 3;

    for (int t = 0; t < TT; ++t) {
        int par = t & 1, op = par ^ 1;

        // ---------- Phase A: [gates_h | q2] = h @ WA^T (2560 x 512) ----------
        {
            const __nv_bfloat16* __restrict__ ah = g_hhi[par];
            const __nv_bfloat16* __restrict__ al = g_hlo[par];
            for (int item = cta; item < 160; item += 128) {
                int n0 = (item % 40) * 64;
                int m0 = (item / 40) * 64;
                float acc[2][4];
#pragma unroll
                for (int nt = 0; nt < 2; ++nt)
#pragma unroll
                    for (int r = 0; r < 4; ++r) acc[nt][r] = 0.f;

                auto issue = [&](int ch) {
                    if (ch < 8) {
                        int c0 = ch * 64;
                        uint32_t buf = sb + (ch & 1) * BUFS;
                        int r = tid >> 3, cu = tid & 7;
                        uint32_t d = buf + r * T_ROW + cu * 16;
                        cp16(d + TA_HI, ah + (m0 + r) * HH + c0 + cu * 8);
                        cp16(d + TA_LO, al + (m0 + r) * HH + c0 + cu * 8);
                        cp16(d + TB_HI, g_WA_hi + (size_t)(n0 + r) * HH + c0 + cu * 8);
                        cp16(d + TB_LO, g_WA_lo + (size_t)(n0 + r) * HH + c0 + cu * 8);
                    }
                    CP_COMMIT();
                };
                issue(0);
                for (int ch = 0; ch < 8; ++ch) {
                    issue(ch + 1);
                    CP_WAIT1();
                    __syncthreads();
                    uint32_t base = sb + (ch & 1) * BUFS;
                    chunk_mma_16w(base + TA_HI, T_SZ, base + TB_HI, T_SZ, mrow, ncol, rowsel, acc);
                    __syncthreads();
                }
#pragma unroll
                for (int nt = 0; nt < 2; ++nt) {
                    int col = n0 + ncol + nt * 8 + cc * 2;
                    int r0 = m0 + mrow + g2, r1 = r0 + 8;
                    if (col < GG) {
                        *(float2*)(g_gates + r0 * GG + col) = make_float2(acc[nt][0], acc[nt][1]);
                        *(float2*)(g_gates + r1 * GG + col) = make_float2(acc[nt][2], acc[nt][3]);
                    } else {
                        int q = col - GG;
                        float b0 = g_bqk[q], b1 = g_bqk[q + 1];
                        *(float2*)(g_q2 + r0 * HH + q) = make_float2(acc[nt][0] + b0, acc[nt][1] + b1);
                        *(float2*)(g_q2 + r1 * HH + q) = make_float2(acc[nt][2] + b0, acc[nt][3] + b1);
                    }
                }
            }
        }
        grid_sync(128);

        // ---------- Phase B: attention, 2 batches per CTA ----------
        {
            int sub = tid >> 8, stid = tid & 255;
            int sw = stid >> 5, ln = stid & 31;
            int b = cta * 2 + sub;

            float qf[16];
            {
                const float4* q4 = (const float4*)(g_q2 + b * HH + ln * 16);
#pragma unroll
                for (int i = 0; i < 4; ++i) {
                    float4 v = q4[i];
                    qf[i * 4 + 0] = v.x; qf[i * 4 + 1] = v.y; qf[i * 4 + 2] = v.z; qf[i * 4 + 3] = v.w;
                }
            }

            float m = -INFINITY, lsum = 0.f;
            float ca[16];
#pragma unroll
            for (int q = 0; q < 16; ++q) ca[q] = 0.f;

            const __nv_bfloat16* hb0 = g_hsb + ((size_t)sw * BB + b) * HH + ln * 16;
            uint4 u0 = *(const uint4*)hb0;
            uint4 u1 = *(const uint4*)(hb0 + 8);

#pragma unroll 4
            for (int it = 0; it < SS / 8; ++it) {
                uint4 c0 = u0, c1 = u1;
                if (it + 1 < SS / 8) {
                    const __nv_bfloat16* hb = g_hsb + ((size_t)(sw + (it + 1) * 8) * BB + b) * HH + ln * 16;
                    u0 = *(const uint4*)hb;
                    u1 = *(const uint4*)(hb + 8);
                }
                float f[16];
                {
                    const __nv_bfloat162* p0 = (const __nv_bfloat162*)&c0;
                    const __nv_bfloat162* p1 = (const __nv_bfloat162*)&c1;
#pragma unroll
                    for (int j = 0; j < 4; ++j) {
                        float2 v = __bfloat1622float2(p0[j]);
                        f[2 * j] = v.x; f[2 * j + 1] = v.y;
                        float2 v2 = __bfloat1622float2(p1[j]);
                        f[8 + 2 * j] = v2.x; f[8 + 2 * j + 1] = v2.y;
                    }
                }
                float dot = 0.f;
#pragma unroll
                for (int q = 0; q < 16; ++q) dot += f[q] * qf[q];
#pragma unroll
                for (int off = 16; off; off >>= 1) dot += __shfl_xor_sync(0xffffffffu, dot, off);
                float mn = fmaxf(m, dot);
                float scl = __expf(m - mn);
                float p = __expf(dot - mn);
                m = mn;
                lsum = lsum * scl + p;
#pragma unroll
                for (int q = 0; q < 16; ++q) ca[q] = ca[q] * scl + p * f[q];
            }

            float* sc = (float*)(smem + sub * ATT_SUB);           // 8 x 512
            float* smx = (float*)(smem + sub * ATT_SUB + 16384);  // 8
            float* slx = (float*)(smem + sub * ATT_SUB + 16416);  // 8
#pragma unroll
            for (int q = 0; q < 16; ++q) sc[sw * HH + ln * 16 + q] = ca[q];
            if (ln == 0) { smx[sw] = m; slx[sw] = lsum; }
            __syncthreads();

            float M = smx[0];
#pragma unroll
            for (int w2 = 1; w2 < 8; ++w2) M = fmaxf(M, smx[w2]);
            float ew[8];
            float L = 0.f;
#pragma unroll
            for (int w2 = 0; w2 < 8; ++w2) { ew[w2] = __expf(smx[w2] - M); L += slx[w2] * ew[w2]; }
            float invL = 1.f / L;
            for (int h = stid; h < HH; h += 256) {
                float v = 0.f;
#pragma unroll
                for (int w2 = 0; w2 < 8; ++w2) v += ew[w2] * sc[w2 * HH + h];
                v *= invL;
                __nv_bfloat16 hi = __float2bfloat16(v);
                g_ctxhi[b * HH + h] = hi;
                g_ctxlo[b * HH + h] = __float2bfloat16(v - __bfloat162float(hi));
            }
        }
        grid_sync(128);

        // ---------- Phase C: gates += ctx @ Wc^T, LSTM epilogue ----------
        {
            int n0 = (cta & 31) * 64;
            int m0 = (cta >> 5) * 64;
            float acc[2][4];
#pragma unroll
            for (int nt = 0; nt < 2; ++nt)
#pragma unroll
                for (int r = 0; r < 4; ++r) acc[nt][r] = 0.f;

            auto issue = [&](int ch) {
                if (ch < 8) {
                    int c0 = ch * 64;
                    uint32_t buf = sb + (ch & 1) * BUFS;
                    int r = tid >> 3, cu = tid & 7;
                    uint32_t d = buf + r * T_ROW + cu * 16;
                    cp16(d + TA_HI, g_ctxhi + (m0 + r) * HH + c0 + cu * 8);
                    cp16(d + TA_LO, g_ctxlo + (m0 + r) * HH + c0 + cu * 8);
                    cp16(d + TB_HI, g_Wc_hi + (size_t)(n0 + r) * HH + c0 + cu * 8);
                    cp16(d + TB_LO, g_Wc_lo + (size_t)(n0 + r) * HH + c0 + cu * 8);
                }
                CP_COMMIT();
            };
            issue(0);
            for (int ch = 0; ch < 8; ++ch) {
                issue(ch + 1);
                CP_WAIT1();
                __syncthreads();
                uint32_t base = sb + (ch & 1) * BUFS;
                chunk_mma_16w(base + TA_HI, T_SZ, base + TB_HI, T_SZ, mrow, ncol, rowsel, acc);
                __syncthreads();
            }

            float* Cs = (float*)smem;
            {
#pragma unroll
                for (int nt = 0; nt < 2; ++nt) {
                    int col = ncol + nt * 8 + cc * 2;
                    int r0 = mrow + g2, r1 = mrow + g2 + 8;
                    Cs[r0 * 68 + col]     = acc[nt][0];
                    Cs[r0 * 68 + col + 1] = acc[nt][1];
                    Cs[r1 * 68 + col]     = acc[nt][2];
                    Cs[r1 * 68 + col + 1] = acc[nt][3];
                }
            }
            __syncthreads();

            int bl_ = tid & 63;
            int q0 = (tid >> 6) * 2;
            int b = m0 + bl_;
            int hbase = n0 >> 2;
#pragma unroll
            for (int q = 0; q < 2; ++q) {
                int hl = q0 + q;
                int jl = hl * 4;
                int jp = n0 + jl;
                const float* gr = g_gates + b * GG + jp;
                float ri = Cs[bl_ * 68 + jl + 0] + gr[0] + g_bd2[jp + 0];
                float rf = Cs[bl_ * 68 + jl + 1] + gr[1] + g_bd2[jp + 1];
                float rg = Cs[bl_ * 68 + jl + 2] + gr[2] + g_bd2[jp + 2];
                float ro = Cs[bl_ * 68 + jl + 3] + gr[3] + g_bd2[jp + 3];
                float ig = 1.f / (1.f + expf(-ri));
                float fg = 1.f / (1.f + expf(-rf));
                float gg = tanhf(rg);
                float og = 1.f / (1.f + expf(-ro));
                int idx = b * HH + hbase + hl;
                float cn = fg * g_c[idx] + ig * gg;
                float hn = og * tanhf(cn);
                g_c[idx] = cn;
                g_hbuf[op][idx] = hn;
                __nv_bfloat16 hi = __float2bfloat16(hn);
                g_hhi[op][idx] = hi;
                g_hlo[op][idx] = __float2bfloat16(hn - __bfloat162float(hi));
            }
        }
        grid_sync(128);

        // ---------- Phase D: output projection (2 batches per CTA, warps 0-1) ----------
        if (w < 2) {
            int b = cta * 2 + w;
            const float* hp = g_hbuf[op] + b * HH;
            float p = 0.f;
#pragma unroll
            for (int q = 0; q < 16; ++q) p += hp[l + (q << 5)] * outW[l + (q << 5)];
#pragma unroll
            for (int off = 16; off; off >>= 1) p += __shfl_xor_sync(0xffffffffu, p, off);
            if (l == 0) out[b * TT + t] = p + outb[0];
        }
    }
}

// ---------------- prep kernels ----------------
__global__ void k_zero() {
    int idx = blockIdx.x * 256 + threadIdx.x;
    if (idx < BB * HH) {
        g_c[idx] = 0.f;
        g_hhi[0][idx] = __float2bfloat16(0.f);
        g_hlo[0][idx] = __float2bfloat16(0.f);
    }
}

__global__ void k_vu(const float* __restrict__ embW, const float* __restrict__ embb,
                     const float* __restrict__ Wih, const float* __restrict__ bih,
                     const float* __restrict__ bhh) {
    int j = blockIdx.x * 256 + threadIdx.x;
    if (j >= GG) return;
    float v = 0.f, u = 0.f;
    const float* wr = Wih + j * RR;
#pragma unroll 8
    for (int r = 0; r < RR; ++r) { v += embW[r] * wr[r]; u += embb[r] * wr[r]; }
    int jp = ((j & (HH - 1)) << 2) | (j >> 9);
    g_v2[jp] = v;
    g_u2[jp] = u + bih[j] + bhh[j];
}

__global__ void k_wenc_split(const float* __restrict__ Whh) {
    int idx = blockIdx.x * 256 + threadIdx.x;
    if (idx >= GG * HH) return;
    int jp = idx >> 9, k = idx & (HH - 1);
    int h = jp >> 2, g = jp & 3;
    float w = Whh[(g * HH + h) * HH + k];
    __nv_bfloat16 hi = __float2bfloat16(w);
    g_Wenc_hi[idx] = hi;
    g_Wenc_lo[idx] = __float2bfloat16(w - __bfloat162float(hi));
}

// gates_h rows of WA (j' gate-interleaved): Wih[:, :512] + Whh; also bd2
__global__ void k_wa_gates(const float* __restrict__ dWih, const float* __restrict__ dWhh,
                           const float* __restrict__ dbih, const float* __restrict__ dbhh) {
    int idx = blockIdx.x * 256 + threadIdx.x;
    if (idx < GG * HH) {
        int jp = idx >> 9, k = idx & (HH - 1);
        int h = jp >> 2, g = jp & 3;
        float w = dWih[(g * HH + h) * K2 + k] + dWhh[(g * HH + h) * HH + k];
        __nv_bfloat16 hi = __float2bfloat16(w);
        g_WA_hi[idx] = hi;
        g_WA_lo[idx] = __float2bfloat16(w - __bfloat162float(hi));
    }
    if (idx < GG) {
        int h = idx >> 2, g = idx & 3;
        g_bd2[idx] = dbih[g * HH + h] + dbhh[g * HH + h];
    }
}

// At rows of WA (rows 2048..2559)
__global__ void k_wa_at() {
    int idx = blockIdx.x * 256 + threadIdx.x;
    if (idx >= HH * HH) return;
    float w = g_At[idx];
    __nv_bfloat16 hi = __float2bfloat16(w);
    size_t d = (size_t)GG * HH + idx;
    g_WA_hi[d] = hi;
    g_WA_lo[d] = __float2bfloat16(w - __bfloat162float(hi));
}

// ctx half: Wih[:, 512:1024]
__global__ void k_wc(const float* __restrict__ dWih) {
    int idx = blockIdx.x * 256 + threadIdx.x;
    if (idx >= GG * HH) return;
    int jp = idx >> 9, k = idx & (HH - 1);
    int h = jp >> 2, g = jp & 3;
    float w = dWih[(g * HH + h) * K2 + HH + k];
    __nv_bfloat16 hi = __float2bfloat16(w);
    g_Wc_hi[idx] = hi;
    g_Wc_lo[idx] = __float2bfloat16(w - __bfloat162float(hi));
}

__global__ void k_bqk(const float* __restrict__ bq, const float* __restrict__ Wk) {
    int m = blockIdx.x * 256 + threadIdx.x;
    if (m >= HH) return;
    float a = 0.f;
    for (int n = 0; n < HH; ++n) a += bq[n] * Wk[n * HH + m];
    g_bqk[m] = a;
}

__global__ void k_transpose512(const float* __restrict__ in, float* __restrict__ out) {
    __shared__ float t[32][33];
    int x = blockIdx.x * 32 + threadIdx.x;
    int y0 = blockIdx.y * 32;
    for (int j = threadIdx.y; j < 32; j += 8) t[j][threadIdx.x] = in[(y0 + j) * HH + x];
    __syncthreads();
    int x2 = y0 + threadIdx.x;
    int y20 = blockIdx.x * 32;
    for (int j = threadIdx.y; j < 32; j += 8) out[(y20 + j) * HH + x2] = t[threadIdx.x][j];
}

__global__ __launch_bounds__(256) void k_gemm_At() {
    __shared__ float As[32][33];
    __shared__ float Bs[32][33];
    int tid = threadIdx.x;
    int m0 = blockIdx.y * 32, n0 = blockIdx.x * 32;
    int lr = tid >> 3, lk = (tid & 7) << 2;
    int ty = tid >> 4, tx = tid & 15;
    float acc00 = 0.f, acc01 = 0.f, acc10 = 0.f, acc11 = 0.f;
    for (int kk = 0; kk < HH; kk += 32) {
        float4 a = *(const float4*)(g_WkT + (m0 + lr) * HH + kk + lk);
        float4 b = *(const float4*)(g_WqT + (n0 + lr) * HH + kk + lk);
        __syncthreads();
        As[lk + 0][lr] = a.x; As[lk + 1][lr] = a.y; As[lk + 2][lr] = a.z; As[lk + 3][lr] = a.w;
        Bs[lk + 0][lr] = b.x; Bs[lk + 1][lr] = b.y; Bs[lk + 2][lr] = b.z; Bs[lk + 3][lr] = b.w;
        __syncthreads();
#pragma unroll
        for (int k = 0; k < 32; ++k) {
            float a0 = As[k][ty * 2], a1 = As[k][ty * 2 + 1];
            float b0 = Bs[k][tx * 2], b1 = Bs[k][tx * 2 + 1];
            acc00 += a0 * b0; acc01 += a0 * b1;
            acc10 += a1 * b0; acc11 += a1 * b1;
        }
    }
    g_At[(m0 + ty * 2 + 0) * HH + n0 + tx * 2 + 0] = acc00;
    g_At[(m0 + ty * 2 + 0) * HH + n0 + tx * 2 + 1] = acc01;
    g_At[(m0 + ty * 2 + 1) * HH + n0 + tx * 2 + 0] = acc10;
    g_At[(m0 + ty * 2 + 1) * HH + n0 + tx * 2 + 1] = acc11;
}

// ---------------- host launcher ----------------
extern "C" void kernel_launch(void* const* d_in, const int* in_sizes, int n_in,
                              void* d_out, int out_size) {
    int off = (n_in >= 18 && in_sizes[1] == 1) ? 1 : 0;
    const float* enc_inputs = (const float*)d_in[0];
    const float* embed_W = (const float*)d_in[1 + off];
    const float* embed_b = (const float*)d_in[2 + off];
    const float* enc_Wih = (const float*)d_in[3 + off];
    const float* enc_Whh = (const float*)d_in[4 + off];
    const float* enc_bih = (const float*)d_in[5 + off];
    const float* enc_bhh = (const float*)d_in[6 + off];
    const float* dec_Wih = (const float*)d_in[7 + off];
    const float* dec_Whh = (const float*)d_in[8 + off];
    const float* dec_bih = (const float*)d_in[9 + off];
    const float* dec_bhh = (const float*)d_in[10 + off];
    const float* Wq = (const float*)d_in[11 + off];
    const float* bq = (const float*)d_in[12 + off];
    const float* Wk = (const float*)d_in[13 + off];
    // bk dropped: uniform over s -> softmax-invariant
    const float* out_W = (const float*)d_in[15 + off];
    const float* out_b = (const float*)d_in[16 + off];
    float* out = (float*)d_out;

    float* g_WkT_p; cudaGetSymbolAddress((void**)&g_WkT_p, g_WkT);
    float* g_WqT_p; cudaGetSymbolAddress((void**)&g_WqT_p, g_WqT);

    cudaFuncSetAttribute(lstm_enc_persist, cudaFuncAttributeMaxDynamicSharedMemorySize, PSMEM);
    cudaFuncSetAttribute(dec_persist, cudaFuncAttributeMaxDynamicSharedMemorySize, SMEM_BYTES);

    // ---- prep ----
    k_zero<<<(BB * HH + 255) / 256, 256>>>();
    k_vu<<<GG / 256, 256>>>(embed_W, embed_b, enc_Wih, enc_bih, enc_bhh);
    k_wenc_split<<<(GG * HH) / 256, 256>>>(enc_Whh);
    k_wa_gates<<<(GG * HH) / 256, 256>>>(dec_Wih, dec_Whh, dec_bih, dec_bhh);
    k_wc<<<(GG * HH) / 256, 256>>>(dec_Wih);
    k_bqk<<<2, 256>>>(bq, Wk);
    dim3 tb(32, 8);
    k_transpose512<<<dim3(16, 16), tb>>>(Wk, g_WkT_p);
    k_transpose512<<<dim3(16, 16), tb>>>(Wq, g_WqT_p);
    k_gemm_At<<<dim3(16, 16), 256>>>();
    k_wa_at<<<(HH * HH) / 256, 256>>>();

    // ---- encoder: ONE persistent kernel, 512 internal steps ----
    lstm_enc_persist<<<dim3(32, 4), 512, PSMEM>>>(enc_inputs);

    // ---- decoder: ONE persistent kernel, 96 internal steps ----
    dec_persist<<<128, 512, SMEM_BYTES>>>(out_W, out_b, out);

    (void)in_sizes; (void)n_in; (void)out_size;
}

// round 8
// speedup vs baseline: 1.0574x; 1.0574x over previous
#include <cuda_runtime.h>
#include <cuda_bf16.h>
#include <math.h>
#include <stdint.h>

#define BB 256
#define SS 512
#define RR 128
#define HH 512
#define TT 96
#define GG 2048   // 4*H
#define K2 1024   // 2*H

// ---------------- device scratch ----------------
__device__ __nv_bfloat16 g_hsb[(size_t)SS * BB * HH];   // encoder hidden states bf16 [s][b][h]
__device__ float g_hbuf[2][BB * HH];                    // ping-pong hidden fp32 (for out proj)
__device__ float g_c[BB * HH];                          // cell state fp32 (decoder)
__device__ __nv_bfloat16 g_hhi[2][BB * HH], g_hlo[2][BB * HH];   // split-bf16 h ping-pong
__device__ __nv_bfloat16 g_ctxhi[BB * HH], g_ctxlo[BB * HH];     // split-bf16 context
__device__ __nv_bfloat16 g_Wenc_hi[GG * HH],  g_Wenc_lo[GG * HH];
__device__ __nv_bfloat16 g_WA_hi[(GG + HH) * HH], g_WA_lo[(GG + HH) * HH]; // [gates_h | At]
__device__ __nv_bfloat16 g_Wc_hi[GG * HH], g_Wc_lo[GG * HH];               // ctx half of dec Wih
__device__ float g_gates[BB * GG];                     // cached gates_h (fp32)
__device__ float g_q2p[2][BB * HH];                    // q2 split-K partials
__device__ float g_v2[GG], g_u2[GG], g_bd2[GG];
__device__ float g_WkT[HH * HH], g_WqT[HH * HH], g_At[HH * HH];
__device__ float g_bqk[HH];

// grid-wide barrier state
__device__ unsigned g_bar_count = 0;
__device__ volatile unsigned g_bar_gen = 0;

// ---------------- helpers ----------------
__device__ __forceinline__ uint32_t smem_u32(const void* p) {
    uint32_t a;
    asm("{ .reg .u64 t; cvta.to.shared.u64 t, %1; cvt.u32.u64 %0, t; }" : "=r"(a) : "l"(p));
    return a;
}
__device__ __forceinline__ void cp16(uint32_t dst, const void* src) {
    asm volatile("cp.async.cg.shared.global [%0], [%1], 16;" :: "r"(dst), "l"(src) : "memory");
}
#define CP_COMMIT() asm volatile("cp.async.commit_group;" ::: "memory")
#define CP_WAIT2()  asm volatile("cp.async.wait_group 2;" ::: "memory")
#define CP_WAIT0()  asm volatile("cp.async.wait_group 0;" ::: "memory")

__device__ __forceinline__ void ldm4(uint32_t* r, uint32_t addr) {
    asm volatile("ldmatrix.sync.aligned.m8n8.x4.shared.b16 {%0,%1,%2,%3}, [%4];"
                 : "=r"(r[0]), "=r"(r[1]), "=r"(r[2]), "=r"(r[3]) : "r"(addr));
}
__device__ __forceinline__ void mma16816(float* c, const uint32_t* a, uint32_t b0, uint32_t b1) {
    asm volatile(
        "mma.sync.aligned.m16n8k16.row.col.f32.bf16.bf16.f32 "
        "{%0,%1,%2,%3}, {%4,%5,%6,%7}, {%8,%9}, {%0,%1,%2,%3};"
        : "+f"(c[0]), "+f"(c[1]), "+f"(c[2]), "+f"(c[3])
        : "r"(a[0]), "r"(a[1]), "r"(a[2]), "r"(a[3]), "r"(b0), "r"(b1));
}

// fast sigmoid/tanh (~2ulp via __expf)
__device__ __forceinline__ float fsig(float x) {
    return __fdividef(1.f, 1.f + __expf(-x));
}
__device__ __forceinline__ float ftanh(float x) {
    float e = __expf(2.f * x);
    return 1.f - __fdividef(2.f, e + 1.f);
}

// hard-spin grid barrier (no nanosleep; detection ~ one L2 round trip)
__device__ __forceinline__ void grid_sync(unsigned nct) {
    __syncthreads();
    if (threadIdx.x == 0) {
        __threadfence();
        unsigned gen = g_bar_gen;
        unsigned t = atomicInc(&g_bar_count, nct - 1);
        if (t == nct - 1) {
            g_bar_gen = gen + 1;
        } else {
            while (g_bar_gen == gen) { }
        }
        __threadfence();
    }
    __syncthreads();
}

// tile geometry
#define T_ROW   144
#define T_SZ    (64 * T_ROW)          // 9216
#define ST_SZ   (4 * T_SZ)            // decoder stage stride 36864
#define SMEM_DEC (4 * ST_SZ)          // 147456 (4 stages)

// persistent encoder smem
#define W_TILE  (8 * T_SZ)            // 73728
#define A_OFF   (2 * W_TILE)          // 147456
#define VU_OFF  (A_OFF + 4 * 2 * T_SZ) // 221184
#define PSMEM   (VU_OFF + 2048)       // 223232

// attention phase smem blocking
#define ATT_SUB 16640                 // sc 16384 + sm 32 + sl 32 (padded)

// ================= 16-warp 64x64 chunk MMA =================
__device__ __forceinline__ void chunk_mma_16w(uint32_t abase, uint32_t alo_off,
                                              uint32_t bbase, uint32_t blo_off,
                                              int mrow, int ncol, uint32_t rowsel,
                                              float acc[2][4]) {
#pragma unroll
    for (int kk = 0; kk < 4; ++kk) {
        uint32_t kof = kk * 32;
        uint32_t aaddr = abase + mrow * T_ROW + rowsel + kof;
        uint32_t baddr = bbase + ncol * T_ROW + rowsel + kof;
        uint32_t ahr[4], alr[4], bh[4], bl2[4];
        ldm4(ahr, aaddr);
        ldm4(alr, aaddr + alo_off);
        ldm4(bh, baddr);
        ldm4(bl2, baddr + blo_off);
#pragma unroll
        for (int nt = 0; nt < 2; ++nt) {
            mma16816(acc[nt], ahr, bh[nt], bh[nt + 2]);
            mma16816(acc[nt], alr, bh[nt], bh[nt + 2]);
            mma16816(acc[nt], ahr, bl2[nt], bl2[nt + 2]);
        }
    }
}

// ================= 4-stage pipelined 64x64 GEMM (decoder; B row stride = HH) =================
// One __syncthreads per chunk: issue distance 3 with 4 buffers makes the
// write of stage (c+3)&3 conflict only with reads of chunk c-1, which are
// bounded by this iteration's barrier.
__device__ __forceinline__ void gemm_pipe(const __nv_bfloat16* __restrict__ ahi,
                                          const __nv_bfloat16* __restrict__ alo,
                                          const __nv_bfloat16* __restrict__ bhi,
                                          const __nv_bfloat16* __restrict__ blo,
                                          int kbase, int nch, uint32_t sb, int tid,
                                          int mrow, int ncol, uint32_t rowsel,
                                          float acc[2][4]) {
    int r = tid >> 3, cu = tid & 7;
    auto issue = [&](int ch) {
        if (ch < nch) {
            size_t c0 = (size_t)kbase + ch * 64 + cu * 8;
            uint32_t d = sb + (ch & 3) * ST_SZ + r * T_ROW + cu * 16;
            size_t ro = (size_t)r * HH + c0;
            cp16(d,            ahi + ro);
            cp16(d +     T_SZ, alo + ro);
            cp16(d + 2 * T_SZ, bhi + ro);
            cp16(d + 3 * T_SZ, blo + ro);
        }
        CP_COMMIT();
    };
    issue(0); issue(1); issue(2);
    for (int ch = 0; ch < nch; ++ch) {
        CP_WAIT2();
        __syncthreads();
        issue(ch + 3);
        uint32_t base = sb + (ch & 3) * ST_SZ;
        chunk_mma_16w(base, T_SZ, base + 2 * T_SZ, T_SZ, mrow, ncol, rowsel, acc);
    }
}

// ================= persistent encoder: W in SMEM, 4-stage A pipeline =================
__global__ __launch_bounds__(512) void lstm_enc_persist(const float* __restrict__ enc_inputs) {
    extern __shared__ char smem[];
    uint32_t sb = smem_u32(smem);
    int tid = threadIdx.x;
    int w = tid >> 5, l = tid & 31;
    int n0 = blockIdx.x * 64;
    int m0 = blockIdx.y * 64;
    int mrow = (w & 3) * 16;
    int ncol = (w >> 2) * 16;

    // weight slice -> SMEM once
    for (int i = tid; i < 4096; i += 512) {
        int c = i >> 9, r = (i >> 3) & 63, cu = i & 7;
        uint32_t d = sb + c * T_SZ + r * T_ROW + cu * 16;
        size_t src = (size_t)(n0 + r) * HH + c * 64 + cu * 8;
        cp16(d, g_Wenc_hi + src);
        cp16(d + W_TILE, g_Wenc_lo + src);
    }
    CP_COMMIT();
    // v/u slice -> SMEM once
    float* sv = (float*)(smem + VU_OFF);
    float* su = sv + 256;
    if (tid < 256) { sv[tid] = g_v2[n0 + tid]; su[tid] = g_u2[n0 + tid]; }
    CP_WAIT0();
    __syncthreads();

    int bl_ = tid & 63;
    int q0 = (tid >> 6) * 2;
    int b = m0 + bl_;
    int hbase = n0 >> 2;
    float creg[2] = {0.f, 0.f};
    uint32_t rowsel = (l & 15) * T_ROW + (l >> 4) * 16;
    int lr = tid >> 3, lcu = tid & 7;

    for (int s = 0; s < SS; ++s) {
        int par = s & 1, op = par ^ 1;
        const __nv_bfloat16* __restrict__ ah = g_hhi[par];
        const __nv_bfloat16* __restrict__ al = g_hlo[par];

        float acc[2][4];
#pragma unroll
        for (int nt = 0; nt < 2; ++nt)
#pragma unroll
            for (int r = 0; r < 4; ++r) acc[nt][r] = 0.f;

        auto issueA = [&](int c) {
            if (c < 8) {
                int c0 = c * 64 + lcu * 8;
                uint32_t d = sb + A_OFF + (c & 3) * (2 * T_SZ) + lr * T_ROW + lcu * 16;
                size_t ro = (size_t)(m0 + lr) * HH + c0;
                cp16(d, ah + ro);
                cp16(d + T_SZ, al + ro);
            }
            CP_COMMIT();
        };

        issueA(0); issueA(1); issueA(2);
        float e = enc_inputs[b * SS + s];
        for (int c = 0; c < 8; ++c) {
            CP_WAIT2();
            __syncthreads();
            issueA(c + 3);
            uint32_t abase = sb + A_OFF + (c & 3) * (2 * T_SZ);
            uint32_t wbase = sb + c * T_SZ;
            chunk_mma_16w(abase, T_SZ, wbase, W_TILE, mrow, ncol, rowsel, acc);
        }

        // epilogue: stage accums in stage-0/1 region (disjoint from stage-3 reads)
        float* Cs = (float*)(smem + A_OFF);
        {
            int g = l >> 2, cc = l & 3;
#pragma unroll
            for (int nt = 0; nt < 2; ++nt) {
                int col = ncol + nt * 8 + cc * 2;
                int r0 = mrow + g, r1 = mrow + g + 8;
                Cs[r0 * 68 + col]     = acc[nt][0];
                Cs[r0 * 68 + col + 1] = acc[nt][1];
                Cs[r1 * 68 + col]     = acc[nt][2];
                Cs[r1 * 68 + col + 1] = acc[nt][3];
            }
        }
        __syncthreads();

#pragma unroll
        for (int q = 0; q < 2; ++q) {
            int hl = q0 + q;
            int jl = hl * 4;
            float ri = Cs[bl_ * 68 + jl + 0] + e * sv[jl + 0] + su[jl + 0];
            float rf = Cs[bl_ * 68 + jl + 1] + e * sv[jl + 1] + su[jl + 1];
            float rg = Cs[bl_ * 68 + jl + 2] + e * sv[jl + 2] + su[jl + 2];
            float ro = Cs[bl_ * 68 + jl + 3] + e * sv[jl + 3] + su[jl + 3];
            float ig = fsig(ri), fg = fsig(rf), gg = ftanh(rg), og = fsig(ro);
            float cn = fg * creg[q] + ig * gg;
            float hn = og * ftanh(cn);
            creg[q] = cn;
            int idx = b * HH + hbase + hl;
            __nv_bfloat16 hi = __float2bfloat16(hn);
            g_hhi[op][idx] = hi;
            g_hlo[op][idx] = __float2bfloat16(hn - __bfloat162float(hi));
            g_hsb[((size_t)s * BB + b) * HH + hbase + hl] = hi;
            if (s == SS - 1) { g_c[idx] = cn; g_hbuf[op][idx] = hn; }
        }
        grid_sync(128);
    }
}

// ================= persistent decoder: 96 steps, balanced phases =================
__global__ __launch_bounds__(512) void dec_persist(const float* __restrict__ outW,
                                                   const float* __restrict__ outb,
                                                   float* __restrict__ out) {
    extern __shared__ char smem[];
    uint32_t sb = smem_u32(smem);
    int tid = threadIdx.x, cta = blockIdx.x;
    int w = tid >> 5, l = tid & 31;
    int mrow = (w & 3) * 16, ncol = (w >> 2) * 16;
    uint32_t rowsel = (l & 15) * T_ROW + (l >> 4) * 16;
    int g2 = l >> 2, cc = l & 3;

    for (int t = 0; t < TT; ++t) {
        int par = t & 1, op = par ^ 1;
        const __nv_bfloat16* __restrict__ ah = g_hhi[par];
        const __nv_bfloat16* __restrict__ al = g_hlo[par];

        // ---------- Phase A round 1: gates_h = h @ Wgates^T (128 tiles, balanced) ----------
        {
            int n0 = (cta & 31) * 64;
            int m0 = (cta >> 5) * 64;
            float acc[2][4];
#pragma unroll
            for (int nt = 0; nt < 2; ++nt)
#pragma unroll
                for (int r = 0; r < 4; ++r) acc[nt][r] = 0.f;
            gemm_pipe(ah + (size_t)m0 * HH, al + (size_t)m0 * HH,
                      g_WA_hi + (size_t)n0 * HH, g_WA_lo + (size_t)n0 * HH,
                      0, 8, sb, tid, mrow, ncol, rowsel, acc);
#pragma unroll
            for (int nt = 0; nt < 2; ++nt) {
                int col = n0 + ncol + nt * 8 + cc * 2;
                int r0 = m0 + mrow + g2, r1 = r0 + 8;
                *(float2*)(g_gates + r0 * GG + col) = make_float2(acc[nt][0], acc[nt][1]);
                *(float2*)(g_gates + r1 * GG + col) = make_float2(acc[nt][2], acc[nt][3]);
            }
        }

        // ---------- Phase A round 2: q2 partials, split-K on 64 CTAs ----------
        if (cta < 64) {
            int half = cta & 1;
            int idx = cta >> 1;
            int nq0 = (idx & 7) * 64;
            int m0 = (idx >> 3) * 64;
            float acc[2][4];
#pragma unroll
            for (int nt = 0; nt < 2; ++nt)
#pragma unroll
                for (int r = 0; r < 4; ++r) acc[nt][r] = 0.f;
            gemm_pipe(ah + (size_t)m0 * HH, al + (size_t)m0 * HH,
                      g_WA_hi + (size_t)(GG + nq0) * HH, g_WA_lo + (size_t)(GG + nq0) * HH,
                      half * 256, 4, sb, tid, mrow, ncol, rowsel, acc);
#pragma unroll
            for (int nt = 0; nt < 2; ++nt) {
                int q = nq0 + ncol + nt * 8 + cc * 2;
                int r0 = m0 + mrow + g2, r1 = r0 + 8;
                float b0 = (half == 0) ? g_bqk[q] : 0.f;
                float b1 = (half == 0) ? g_bqk[q + 1] : 0.f;
                *(float2*)(g_q2p[half] + r0 * HH + q) = make_float2(acc[nt][0] + b0, acc[nt][1] + b1);
                *(float2*)(g_q2p[half] + r1 * HH + q) = make_float2(acc[nt][2] + b0, acc[nt][3] + b1);
            }
        }
        grid_sync(128);

        // ---------- Phase B: attention, 2 batches per CTA ----------
        {
            int sub = tid >> 8, stid = tid & 255;
            int sw = stid >> 5, ln = stid & 31;
            int b = cta * 2 + sub;

            float qf[16];
            {
                const float4* qa = (const float4*)(g_q2p[0] + b * HH + ln * 16);
                const float4* qb = (const float4*)(g_q2p[1] + b * HH + ln * 16);
#pragma unroll
                for (int i = 0; i < 4; ++i) {
                    float4 va = qa[i], vb = qb[i];
                    qf[i * 4 + 0] = va.x + vb.x; qf[i * 4 + 1] = va.y + vb.y;
                    qf[i * 4 + 2] = va.z + vb.z; qf[i * 4 + 3] = va.w + vb.w;
                }
            }

            float m = -INFINITY, lsum = 0.f;
            float ca[16];
#pragma unroll
            for (int q = 0; q < 16; ++q) ca[q] = 0.f;

            const __nv_bfloat16* hb0 = g_hsb + ((size_t)sw * BB + b) * HH + ln * 16;
            uint4 u0 = *(const uint4*)hb0;
            uint4 u1 = *(const uint4*)(hb0 + 8);

#pragma unroll 4
            for (int it = 0; it < SS / 8; ++it) {
                uint4 c0 = u0, c1 = u1;
                if (it + 1 < SS / 8) {
                    const __nv_bfloat16* hb = g_hsb + ((size_t)(sw + (it + 1) * 8) * BB + b) * HH + ln * 16;
                    u0 = *(const uint4*)hb;
                    u1 = *(const uint4*)(hb + 8);
                }
                float f[16];
                {
                    const __nv_bfloat162* p0 = (const __nv_bfloat162*)&c0;
                    const __nv_bfloat162* p1 = (const __nv_bfloat162*)&c1;
#pragma unroll
                    for (int j = 0; j < 4; ++j) {
                        float2 v = __bfloat1622float2(p0[j]);
                        f[2 * j] = v.x; f[2 * j + 1] = v.y;
                        float2 v2 = __bfloat1622float2(p1[j]);
                        f[8 + 2 * j] = v2.x; f[8 + 2 * j + 1] = v2.y;
                    }
                }
                float dot = 0.f;
#pragma unroll
                for (int q = 0; q < 16; ++q) dot += f[q] * qf[q];
#pragma unroll
                for (int off = 16; off; off >>= 1) dot += __shfl_xor_sync(0xffffffffu, dot, off);
                float mn = fmaxf(m, dot);
                float scl = __expf(m - mn);
                float p = __expf(dot - mn);
                m = mn;
                lsum = lsum * scl + p;
#pragma unroll
                for (int q = 0; q < 16; ++q) ca[q] = ca[q] * scl + p * f[q];
            }

            float* sc = (float*)(smem + sub * ATT_SUB);
            float* smx = (float*)(smem + sub * ATT_SUB + 16384);
            float* slx = (float*)(smem + sub * ATT_SUB + 16416);
#pragma unroll
            for (int q = 0; q < 16; ++q) sc[sw * HH + ln * 16 + q] = ca[q];
            if (ln == 0) { smx[sw] = m; slx[sw] = lsum; }
            __syncthreads();

            float M = smx[0];
#pragma unroll
            for (int w2 = 1; w2 < 8; ++w2) M = fmaxf(M, smx[w2]);
            float ew[8];
            float L = 0.f;
#pragma unroll
            for (int w2 = 0; w2 < 8; ++w2) { ew[w2] = __expf(smx[w2] - M); L += slx[w2] * ew[w2]; }
            float invL = __fdividef(1.f, L);
            for (int h = stid; h < HH; h += 256) {
                float v = 0.f;
#pragma unroll
                for (int w2 = 0; w2 < 8; ++w2) v += ew[w2] * sc[w2 * HH + h];
                v *= invL;
                __nv_bfloat16 hi = __float2bfloat16(v);
                g_ctxhi[b * HH + h] = hi;
                g_ctxlo[b * HH + h] = __float2bfloat16(v - __bfloat162float(hi));
            }
        }
        grid_sync(128);

        // ---------- Phase C: gates += ctx @ Wc^T, LSTM epilogue ----------
        {
            int n0 = (cta & 31) * 64;
            int m0 = (cta >> 5) * 64;
            float acc[2][4];
#pragma unroll
            for (int nt = 0; nt < 2; ++nt)
#pragma unroll
                for (int r = 0; r < 4; ++r) acc[nt][r] = 0.f;
            gemm_pipe(g_ctxhi + (size_t)m0 * HH, g_ctxlo + (size_t)m0 * HH,
                      g_Wc_hi + (size_t)n0 * HH, g_Wc_lo + (size_t)n0 * HH,
                      0, 8, sb, tid, mrow, ncol, rowsel, acc);

            float* Cs = (float*)smem;   // stage-0 region; disjoint from stage-3 reads
            {
#pragma unroll
                for (int nt = 0; nt < 2; ++nt) {
                    int col = ncol + nt * 8 + cc * 2;
                    int r0 = mrow + g2, r1 = mrow + g2 + 8;
                    Cs[r0 * 68 + col]     = acc[nt][0];
                    Cs[r0 * 68 + col + 1] = acc[nt][1];
                    Cs[r1 * 68 + col]     = acc[nt][2];
                    Cs[r1 * 68 + col + 1] = acc[nt][3];
                }
            }
            __syncthreads();

            int bl_ = tid & 63;
            int q0 = (tid >> 6) * 2;
            int b = m0 + bl_;
            int hbase = n0 >> 2;
#pragma unroll
            for (int q = 0; q < 2; ++q) {
                int hl = q0 + q;
                int jl = hl * 4;
                int jp = n0 + jl;
                const float* gr = g_gates + b * GG + jp;
                float ri = Cs[bl_ * 68 + jl + 0] + gr[0] + g_bd2[jp + 0];
                float rf = Cs[bl_ * 68 + jl + 1] + gr[1] + g_bd2[jp + 1];
                float rg = Cs[bl_ * 68 + jl + 2] + gr[2] + g_bd2[jp + 2];
                float ro = Cs[bl_ * 68 + jl + 3] + gr[3] + g_bd2[jp + 3];
                float ig = fsig(ri), fg = fsig(rf), gg = ftanh(rg), og = fsig(ro);
                int idx = b * HH + hbase + hl;
                float cn = fg * g_c[idx] + ig * gg;
                float hn = og * ftanh(cn);
                g_c[idx] = cn;
                g_hbuf[op][idx] = hn;
                __nv_bfloat16 hi = __float2bfloat16(hn);
                g_hhi[op][idx] = hi;
                g_hlo[op][idx] = __float2bfloat16(hn - __bfloat162float(hi));
            }
        }
        grid_sync(128);

        // ---------- Phase D: output projection (cheap, no trailing sync needed) ----------
        if (w < 2) {
            int b = cta * 2 + w;
            const float* hp = g_hbuf[op] + b * HH;
            float p = 0.f;
#pragma unroll
            for (int q = 0; q < 16; ++q) p += hp[l + (q << 5)] * outW[l + (q << 5)];
#pragma unroll
            for (int off = 16; off; off >>= 1) p += __shfl_xor_sync(0xffffffffu, p, off);
            if (l == 0) out[b * TT + t] = p + outb[0];
        }
    }
}

// ---------------- prep kernels ----------------
__global__ void k_zero() {
    int idx = blockIdx.x * 256 + threadIdx.x;
    if (idx < BB * HH) {
        g_c[idx] = 0.f;
        g_hhi[0][idx] = __float2bfloat16(0.f);
        g_hlo[0][idx] = __float2bfloat16(0.f);
    }
}

__global__ void k_vu(const float* __restrict__ embW, const float* __restrict__ embb,
                     const float* __restrict__ Wih, const float* __restrict__ bih,
                     const float* __restrict__ bhh) {
    int j = blockIdx.x * 256 + threadIdx.x;
    if (j >= GG) return;
    float v = 0.f, u = 0.f;
    const float* wr = Wih + j * RR;
#pragma unroll 8
    for (int r = 0; r < RR; ++r) { v += embW[r] * wr[r]; u += embb[r] * wr[r]; }
    int jp = ((j & (HH - 1)) << 2) | (j >> 9);
    g_v2[jp] = v;
    g_u2[jp] = u + bih[j] + bhh[j];
}

__global__ void k_wenc_split(const float* __restrict__ Whh) {
    int idx = blockIdx.x * 256 + threadIdx.x;
    if (idx >= GG * HH) return;
    int jp = idx >> 9, k = idx & (HH - 1);
    int h = jp >> 2, g = jp & 3;
    float w = Whh[(g * HH + h) * HH + k];
    __nv_bfloat16 hi = __float2bfloat16(w);
    g_Wenc_hi[idx] = hi;
    g_Wenc_lo[idx] = __float2bfloat16(w - __bfloat162float(hi));
}

__global__ void k_wa_gates(const float* __restrict__ dWih, const float* __restrict__ dWhh,
                           const float* __restrict__ dbih, const float* __restrict__ dbhh) {
    int idx = blockIdx.x * 256 + threadIdx.x;
    if (idx < GG * HH) {
        int jp = idx >> 9, k = idx & (HH - 1);
        int h = jp >> 2, g = jp & 3;
        float w = dWih[(g * HH + h) * K2 + k] + dWhh[(g * HH + h) * HH + k];
        __nv_bfloat16 hi = __float2bfloat16(w);
        g_WA_hi[idx] = hi;
        g_WA_lo[idx] = __float2bfloat16(w - __bfloat162float(hi));
    }
    if (idx < GG) {
        int h = idx >> 2, g = idx & 3;
        g_bd2[idx] = dbih[g * HH + h] + dbhh[g * HH + h];
    }
}

__global__ void k_wa_at() {
    int idx = blockIdx.x * 256 + threadIdx.x;
    if (idx >= HH * HH) return;
    float w = g_At[idx];
    __nv_bfloat16 hi = __float2bfloat16(w);
    size_t d = (size_t)GG * HH + idx;
    g_WA_hi[d] = hi;
    g_WA_lo[d] = __float2bfloat16(w - __bfloat162float(hi));
}

__global__ void k_wc(const float* __restrict__ dWih) {
    int idx = blockIdx.x * 256 + threadIdx.x;
    if (idx >= GG * HH) return;
    int jp = idx >> 9, k = idx & (HH - 1);
    int h = jp >> 2, g = jp & 3;
    float w = dWih[(g * HH + h) * K2 + HH + k];
    __nv_bfloat16 hi = __float2bfloat16(w);
    g_Wc_hi[idx] = hi;
    g_Wc_lo[idx] = __float2bfloat16(w - __bfloat162float(hi));
}

// bqk[m] = sum_n bq[n] * WkT[m][n]  (row-contiguous; warp per m)
__global__ void k_bqk2(const float* __restrict__ bq) {
    int m = blockIdx.x * 8 + (threadIdx.x >> 5);
    int ln = threadIdx.x & 31;
    const float* row = g_WkT + (size_t)m * HH;
    float a = 0.f;
    for (int n = ln; n < HH; n += 32) a += bq[n] * row[n];
#pragma unroll
    for (int off = 16; off; off >>= 1) a += __shfl_xor_sync(0xffffffffu, a, off);
    if (ln == 0) g_bqk[m] = a;
}

__global__ void k_transpose512(const float* __restrict__ in, float* __restrict__ out) {
    __shared__ float t[32][33];
    int x = blockIdx.x * 32 + threadIdx.x;
    int y0 = blockIdx.y * 32;
    for (int j = threadIdx.y; j < 32; j += 8) t[j][threadIdx.x] = in[(y0 + j) * HH + x];
    __syncthreads();
    int x2 = y0 + threadIdx.x;
    int y20 = blockIdx.x * 32;
    for (int j = threadIdx.y; j < 32; j += 8) out[(y20 + j) * HH + x2] = t[threadIdx.x][j];
}

__global__ __launch_bounds__(256) void k_gemm_At() {
    __shared__ float As[32][33];
    __shared__ float Bs[32][33];
    int tid = threadIdx.x;
    int m0 = blockIdx.y * 32, n0 = blockIdx.x * 32;
    int lr = tid >> 3, lk = (tid & 7) << 2;
    int ty = tid >> 4, tx = tid & 15;
    float acc00 = 0.f, acc01 = 0.f, acc10 = 0.f, acc11 = 0.f;
    for (int kk = 0; kk < HH; kk += 32) {
        float4 a = *(const float4*)(g_WkT + (m0 + lr) * HH + kk + lk);
        float4 b = *(const float4*)(g_WqT + (n0 + lr) * HH + kk + lk);
        __syncthreads();
        As[lk + 0][lr] = a.x; As[lk + 1][lr] = a.y; As[lk + 2][lr] = a.z; As[lk + 3][lr] = a.w;
        Bs[lk + 0][lr] = b.x; Bs[lk + 1][lr] = b.y; Bs[lk + 2][lr] = b.z; Bs[lk + 3][lr] = b.w;
        __syncthreads();
#pragma unroll
        for (int k = 0; k < 32; ++k) {
            float a0 = As[k][ty * 2], a1 = As[k][ty * 2 + 1];
            float b0 = Bs[k][tx * 2], b1 = Bs[k][tx * 2 + 1];
            acc00 += a0 * b0; acc01 += a0 * b1;
            acc10 += a1 * b0; acc11 += a1 * b1;
        }
    }
    g_At[(m0 + ty * 2 + 0) * HH + n0 + tx * 2 + 0] = acc00;
    g_At[(m0 + ty * 2 + 0) * HH + n0 + tx * 2 + 1] = acc01;
    g_At[(m0 + ty * 2 + 1) * HH + n0 + tx * 2 + 0] = acc10;
    g_At[(m0 + ty * 2 + 1) * HH + n0 + tx * 2 + 1] = acc11;
}

// ---------------- host launcher ----------------
extern "C" void kernel_launch(void* const* d_in, const int* in_sizes, int n_in,
                              void* d_out, int out_size) {
    int off = (n_in >= 18 && in_sizes[1] == 1) ? 1 : 0;
    const float* enc_inputs = (const float*)d_in[0];
    const float* embed_W = (const float*)d_in[1 + off];
    const float* embed_b = (const float*)d_in[2 + off];
    const float* enc_Wih = (const float*)d_in[3 + off];
    const float* enc_Whh = (const float*)d_in[4 + off];
    const float* enc_bih = (const float*)d_in[5 + off];
    const float* enc_bhh = (const float*)d_in[6 + off];
    const float* dec_Wih = (const float*)d_in[7 + off];
    const float* dec_Whh = (const float*)d_in[8 + off];
    const float* dec_bih = (const float*)d_in[9 + off];
    const float* dec_bhh = (const float*)d_in[10 + off];
    const float* Wq = (const float*)d_in[11 + off];
    const float* bq = (const float*)d_in[12 + off];
    const float* Wk = (const float*)d_in[13 + off];
    // bk dropped: uniform over s -> softmax-invariant
    const float* out_W = (const float*)d_in[15 + off];
    const float* out_b = (const float*)d_in[16 + off];
    float* out = (float*)d_out;

    float* g_WkT_p; cudaGetSymbolAddress((void**)&g_WkT_p, g_WkT);
    float* g_WqT_p; cudaGetSymbolAddress((void**)&g_WqT_p, g_WqT);

    cudaFuncSetAttribute(lstm_enc_persist, cudaFuncAttributeMaxDynamicSharedMemorySize, PSMEM);
    cudaFuncSetAttribute(dec_persist, cudaFuncAttributeMaxDynamicSharedMemorySize, SMEM_DEC);

    // ---- prep ----
    k_zero<<<(BB * HH + 255) / 256, 256>>>();
    k_vu<<<GG / 256, 256>>>(embed_W, embed_b, enc_Wih, enc_bih, enc_bhh);
    k_wenc_split<<<(GG * HH) / 256, 256>>>(enc_Whh);
    k_wa_gates<<<(GG * HH) / 256, 256>>>(dec_Wih, dec_Whh, dec_bih, dec_bhh);
    k_wc<<<(GG * HH) / 256, 256>>>(dec_Wih);
    dim3 tb(32, 8);
    k_transpose512<<<dim3(16, 16), tb>>>(Wk, g_WkT_p);
    k_transpose512<<<dim3(16, 16), tb>>>(Wq, g_WqT_p);
    k_bqk2<<<64, 256>>>(bq);
    k_gemm_At<<<dim3(16, 16), 256>>>();
    k_wa_at<<<(HH * HH) / 256, 256>>>();

    // ---- encoder: ONE persistent kernel, 512 internal steps ----
    lstm_enc_persist<<<dim3(32, 4), 512, PSMEM>>>(enc_inputs);

    // ---- decoder: ONE persistent kernel, 96 internal steps ----
    dec_persist<<<128, 512, SMEM_DEC>>>(out_W, out_b, out);

    (void)in_sizes; (void)n_in; (void)out_size;
}

// round 9
// speedup vs baseline: 1.4002x; 1.3241x over previous
#include <cuda_runtime.h>
#include <cuda_bf16.h>
#include <math.h>
#include <stdint.h>

#define BB 256
#define SS 512
#define RR 128
#define HH 512
#define TT 96
#define GG 2048   // 4*H
#define K2 1024   // 2*H

// ---------------- device scratch ----------------
__device__ __nv_bfloat16 g_hsb[(size_t)SS * BB * HH];   // encoder hidden states bf16 [s][b][h]
__device__ float g_hbuf[2][BB * HH];                    // ping-pong hidden fp32 (for out proj)
__device__ float g_c[BB * HH];                          // cell state fp32 (decoder)
__device__ __nv_bfloat16 g_hhi[2][BB * HH], g_hlo[2][BB * HH];   // split-bf16 h ping-pong
__device__ __nv_bfloat16 g_ctxhi[BB * HH], g_ctxlo[BB * HH];     // split-bf16 context
__device__ __nv_bfloat16 g_Wenc_hi[GG * HH],  g_Wenc_lo[GG * HH];
__device__ __nv_bfloat16 g_WA_hi[(GG + HH) * HH], g_WA_lo[(GG + HH) * HH]; // [gates_h | At]
__device__ __nv_bfloat16 g_Wc_hi[GG * HH], g_Wc_lo[GG * HH];               // ctx half of dec Wih
__device__ float g_gates[BB * GG];                     // cached gates_h (fp32)
__device__ float g_q2p[4][BB * HH];                    // q2 split-K partials (4-way)
__device__ float g_v2[GG], g_u2[GG], g_bd2[GG];
__device__ float g_WkT[HH * HH], g_WqT[HH * HH];
__device__ float g_bqk[HH];

// grid-wide barrier state
__device__ unsigned g_bar_count = 0;
__device__ volatile unsigned g_bar_gen = 0;

// ---------------- helpers ----------------
__device__ __forceinline__ uint32_t smem_u32(const void* p) {
    uint32_t a;
    asm("{ .reg .u64 t; cvta.to.shared.u64 t, %1; cvt.u32.u64 %0, t; }" : "=r"(a) : "l"(p));
    return a;
}
__device__ __forceinline__ void cp16(uint32_t dst, const void* src) {
    asm volatile("cp.async.cg.shared.global [%0], [%1], 16;" :: "r"(dst), "l"(src) : "memory");
}
#define CP_COMMIT() asm volatile("cp.async.commit_group;" ::: "memory")
#define CP_WAIT2()  asm volatile("cp.async.wait_group 2;" ::: "memory")
#define CP_WAIT0()  asm volatile("cp.async.wait_group 0;" ::: "memory")

__device__ __forceinline__ void ldm4(uint32_t* r, uint32_t addr) {
    asm volatile("ldmatrix.sync.aligned.m8n8.x4.shared.b16 {%0,%1,%2,%3}, [%4];"
                 : "=r"(r[0]), "=r"(r[1]), "=r"(r[2]), "=r"(r[3]) : "r"(addr));
}
__device__ __forceinline__ void mma16816(float* c, const uint32_t* a, uint32_t b0, uint32_t b1) {
    asm volatile(
        "mma.sync.aligned.m16n8k16.row.col.f32.bf16.bf16.f32 "
        "{%0,%1,%2,%3}, {%4,%5,%6,%7}, {%8,%9}, {%0,%1,%2,%3};"
        : "+f"(c[0]), "+f"(c[1]), "+f"(c[2]), "+f"(c[3])
        : "r"(a[0]), "r"(a[1]), "r"(a[2]), "r"(a[3]), "r"(b0), "r"(b1));
}

// fast sigmoid/tanh (~2ulp via __expf)
__device__ __forceinline__ float fsig(float x) {
    return __fdividef(1.f, 1.f + __expf(-x));
}
__device__ __forceinline__ float ftanh(float x) {
    float e = __expf(2.f * x);
    return 1.f - __fdividef(2.f, e + 1.f);
}

// hard-spin grid barrier
__device__ __forceinline__ void grid_sync(unsigned nct) {
    __syncthreads();
    if (threadIdx.x == 0) {
        __threadfence();
        unsigned gen = g_bar_gen;
        unsigned t = atomicInc(&g_bar_count, nct - 1);
        if (t == nct - 1) {
            g_bar_gen = gen + 1;
        } else {
            while (g_bar_gen == gen) { }
        }
        __threadfence();
    }
    __syncthreads();
}

// tile geometry
#define T_ROW   144
#define T_SZ    (64 * T_ROW)          // 9216
#define ST_SZ   (4 * T_SZ)            // decoder stage stride 36864
#define SMEM_DEC (4 * ST_SZ)          // 147456 (4 stages)

// persistent encoder smem
#define W_TILE  (8 * T_SZ)            // 73728
#define A_OFF   (2 * W_TILE)          // 147456
#define VU_OFF  (A_OFF + 4 * 2 * T_SZ) // 221184
#define PSMEM   (VU_OFF + 2048)       // 223232

// attention phase smem blocking
#define ATT_SUB 16640                 // sc 16384 + sm 32 + sl 32 (padded)

// ================= 16-warp 64x64 chunk MMA =================
__device__ __forceinline__ void chunk_mma_16w(uint32_t abase, uint32_t alo_off,
                                              uint32_t bbase, uint32_t blo_off,
                                              int mrow, int ncol, uint32_t rowsel,
                                              float acc[2][4]) {
#pragma unroll
    for (int kk = 0; kk < 4; ++kk) {
        uint32_t kof = kk * 32;
        uint32_t aaddr = abase + mrow * T_ROW + rowsel + kof;
        uint32_t baddr = bbase + ncol * T_ROW + rowsel + kof;
        uint32_t ahr[4], alr[4], bh[4], bl2[4];
        ldm4(ahr, aaddr);
        ldm4(alr, aaddr + alo_off);
        ldm4(bh, baddr);
        ldm4(bl2, baddr + blo_off);
#pragma unroll
        for (int nt = 0; nt < 2; ++nt) {
            mma16816(acc[nt], ahr, bh[nt], bh[nt + 2]);
            mma16816(acc[nt], alr, bh[nt], bh[nt + 2]);
            mma16816(acc[nt], ahr, bl2[nt], bl2[nt + 2]);
        }
    }
}

// ================= 4-stage pipelined 64x64 GEMM (decoder; row stride = HH) =================
__device__ __forceinline__ void gemm_pipe(const __nv_bfloat16* __restrict__ ahi,
                                          const __nv_bfloat16* __restrict__ alo,
                                          const __nv_bfloat16* __restrict__ bhi,
                                          const __nv_bfloat16* __restrict__ blo,
                                          int kbase, int nch, uint32_t sb, int tid,
                                          int mrow, int ncol, uint32_t rowsel,
                                          float acc[2][4]) {
    int r = tid >> 3, cu = tid & 7;
    auto issue = [&](int ch) {
        if (ch < nch) {
            size_t c0 = (size_t)kbase + ch * 64 + cu * 8;
            uint32_t d = sb + (ch & 3) * ST_SZ + r * T_ROW + cu * 16;
            size_t ro = (size_t)r * HH + c0;
            cp16(d,            ahi + ro);
            cp16(d +     T_SZ, alo + ro);
            cp16(d + 2 * T_SZ, bhi + ro);
            cp16(d + 3 * T_SZ, blo + ro);
        }
        CP_COMMIT();
    };
    issue(0); issue(1); issue(2);
    for (int ch = 0; ch < nch; ++ch) {
        CP_WAIT2();
        __syncthreads();
        issue(ch + 3);
        uint32_t base = sb + (ch & 3) * ST_SZ;
        chunk_mma_16w(base, T_SZ, base + 2 * T_SZ, T_SZ, mrow, ncol, rowsel, acc);
    }
}

// ================= persistent encoder =================
__global__ __launch_bounds__(512) void lstm_enc_persist(const float* __restrict__ enc_inputs) {
    extern __shared__ char smem[];
    uint32_t sb = smem_u32(smem);
    int tid = threadIdx.x;
    int w = tid >> 5, l = tid & 31;
    int n0 = blockIdx.x * 64;
    int m0 = blockIdx.y * 64;
    int mrow = (w & 3) * 16;
    int ncol = (w >> 2) * 16;

    // weight slice -> SMEM once
    for (int i = tid; i < 4096; i += 512) {
        int c = i >> 9, r = (i >> 3) & 63, cu = i & 7;
        uint32_t d = sb + c * T_SZ + r * T_ROW + cu * 16;
        size_t src = (size_t)(n0 + r) * HH + c * 64 + cu * 8;
        cp16(d, g_Wenc_hi + src);
        cp16(d + W_TILE, g_Wenc_lo + src);
    }
    CP_COMMIT();
    float* sv = (float*)(smem + VU_OFF);
    float* su = sv + 256;
    if (tid < 256) { sv[tid] = g_v2[n0 * 4 / 4 + tid]; su[tid] = g_u2[n0 + tid]; }
    if (tid < 256) sv[tid] = g_v2[n0 + tid];
    CP_WAIT0();
    __syncthreads();

    // epilogue ownership: thread = (batch row, h-pair); coalesced bf162 stores
    int bnew = tid >> 3;          // 0..63
    int kp = tid & 7;             // 0..7
    int b = m0 + bnew;
    int hl0 = kp * 2;
    int hbase = n0 >> 2;
    float creg[2] = {0.f, 0.f};
    uint32_t rowsel = (l & 15) * T_ROW + (l >> 4) * 16;
    int lr = tid >> 3, lcu = tid & 7;

    for (int s = 0; s < SS; ++s) {
        int par = s & 1, op = par ^ 1;
        const __nv_bfloat16* __restrict__ ah = g_hhi[par];
        const __nv_bfloat16* __restrict__ al = g_hlo[par];

        float acc[2][4];
#pragma unroll
        for (int nt = 0; nt < 2; ++nt)
#pragma unroll
            for (int r = 0; r < 4; ++r) acc[nt][r] = 0.f;

        auto issueA = [&](int c) {
            if (c < 8) {
                int c0 = c * 64 + lcu * 8;
                uint32_t d = sb + A_OFF + (c & 3) * (2 * T_SZ) + lr * T_ROW + lcu * 16;
                size_t ro = (size_t)(m0 + lr) * HH + c0;
                cp16(d, ah + ro);
                cp16(d + T_SZ, al + ro);
            }
            CP_COMMIT();
        };

        issueA(0); issueA(1); issueA(2);
        float e = enc_inputs[b * SS + s];
        for (int c = 0; c < 8; ++c) {
            CP_WAIT2();
            __syncthreads();
            issueA(c + 3);
            uint32_t abase = sb + A_OFF + (c & 3) * (2 * T_SZ);
            uint32_t wbase = sb + c * T_SZ;
            chunk_mma_16w(abase, T_SZ, wbase, W_TILE, mrow, ncol, rowsel, acc);
        }

        // stage accums in stage-0/1 region (disjoint from stage-3 trailing reads)
        float* Cs = (float*)(smem + A_OFF);
        {
            int g = l >> 2, cc = l & 3;
#pragma unroll
            for (int nt = 0; nt < 2; ++nt) {
                int col = ncol + nt * 8 + cc * 2;
                int r0 = mrow + g, r1 = mrow + g + 8;
                Cs[r0 * 68 + col]     = acc[nt][0];
                Cs[r0 * 68 + col + 1] = acc[nt][1];
                Cs[r1 * 68 + col]     = acc[nt][2];
                Cs[r1 * 68 + col + 1] = acc[nt][3];
            }
        }
        __syncthreads();

        float4 c0 = *(float4*)&Cs[bnew * 68 + kp * 8];
        float4 c1 = *(float4*)&Cs[bnew * 68 + kp * 8 + 4];
        float4 v0 = *(float4*)&sv[kp * 8], v1 = *(float4*)&sv[kp * 8 + 4];
        float4 u0 = *(float4*)&su[kp * 8], u1 = *(float4*)&su[kp * 8 + 4];

        float h0, h1;
        {
            float ig = fsig(c0.x + e * v0.x + u0.x);
            float fg = fsig(c0.y + e * v0.y + u0.y);
            float gg = ftanh(c0.z + e * v0.z + u0.z);
            float og = fsig(c0.w + e * v0.w + u0.w);
            float cn = fg * creg[0] + ig * gg;
            h0 = og * ftanh(cn);
            creg[0] = cn;
        }
        {
            float ig = fsig(c1.x + e * v1.x + u1.x);
            float fg = fsig(c1.y + e * v1.y + u1.y);
            float gg = ftanh(c1.z + e * v1.z + u1.z);
            float og = fsig(c1.w + e * v1.w + u1.w);
            float cn = fg * creg[1] + ig * gg;
            h1 = og * ftanh(cn);
            creg[1] = cn;
        }
        int idx = b * HH + hbase + hl0;
        __nv_bfloat16 b0 = __float2bfloat16(h0), b1 = __float2bfloat16(h1);
        __nv_bfloat162 hi2; hi2.x = b0; hi2.y = b1;
        __nv_bfloat162 lo2;
        lo2.x = __float2bfloat16(h0 - __bfloat162float(b0));
        lo2.y = __float2bfloat16(h1 - __bfloat162float(b1));
        *(__nv_bfloat162*)&g_hhi[op][idx] = hi2;
        *(__nv_bfloat162*)&g_hlo[op][idx] = lo2;
        *(__nv_bfloat162*)&g_hsb[((size_t)s * BB + b) * HH + hbase + hl0] = hi2;
        if (s == SS - 1) {
            *(float2*)&g_c[idx] = make_float2(creg[0], creg[1]);
            *(float2*)&g_hbuf[op][idx] = make_float2(h0, h1);
        }
        grid_sync(128);
    }
}

// ================= persistent decoder: 96 steps, balanced phases =================
__global__ __launch_bounds__(512) void dec_persist(const float* __restrict__ outW,
                                                   const float* __restrict__ outb,
                                                   float* __restrict__ out) {
    extern __shared__ char smem[];
    uint32_t sb = smem_u32(smem);
    int tid = threadIdx.x, cta = blockIdx.x;
    int w = tid >> 5, l = tid & 31;
    int mrow = (w & 3) * 16, ncol = (w >> 2) * 16;
    uint32_t rowsel = (l & 15) * T_ROW + (l >> 4) * 16;
    int g2 = l >> 2, cc = l & 3;

    for (int t = 0; t < TT; ++t) {
        int par = t & 1, op = par ^ 1;
        const __nv_bfloat16* __restrict__ ah = g_hhi[par];
        const __nv_bfloat16* __restrict__ al = g_hlo[par];

        // ---------- Phase A round 1: gates_h (128 tiles, 1/CTA) ----------
        {
            int n0 = (cta & 31) * 64;
            int m0 = (cta >> 5) * 64;
            float acc[2][4];
#pragma unroll
            for (int nt = 0; nt < 2; ++nt)
#pragma unroll
                for (int r = 0; r < 4; ++r) acc[nt][r] = 0.f;
            gemm_pipe(ah + (size_t)m0 * HH, al + (size_t)m0 * HH,
                      g_WA_hi + (size_t)n0 * HH, g_WA_lo + (size_t)n0 * HH,
                      0, 8, sb, tid, mrow, ncol, rowsel, acc);
#pragma unroll
            for (int nt = 0; nt < 2; ++nt) {
                int col = n0 + ncol + nt * 8 + cc * 2;
                int r0 = m0 + mrow + g2, r1 = r0 + 8;
                *(float2*)(g_gates + r0 * GG + col) = make_float2(acc[nt][0], acc[nt][1]);
                *(float2*)(g_gates + r1 * GG + col) = make_float2(acc[nt][2], acc[nt][3]);
            }
        }

        // ---------- Phase A round 2: q2 partials, 4-way split-K (128 pieces, 1/CTA) ----------
        {
            int quarter = cta & 3;
            int idx = cta >> 2;            // 0..31
            int nq0 = (idx & 7) * 64;
            int m0 = (idx >> 3) * 64;
            float acc[2][4];
#pragma unroll
            for (int nt = 0; nt < 2; ++nt)
#pragma unroll
                for (int r = 0; r < 4; ++r) acc[nt][r] = 0.f;
            gemm_pipe(ah + (size_t)m0 * HH, al + (size_t)m0 * HH,
                      g_WA_hi + (size_t)(GG + nq0) * HH, g_WA_lo + (size_t)(GG + nq0) * HH,
                      quarter * 128, 2, sb, tid, mrow, ncol, rowsel, acc);
#pragma unroll
            for (int nt = 0; nt < 2; ++nt) {
                int q = nq0 + ncol + nt * 8 + cc * 2;
                int r0 = m0 + mrow + g2, r1 = r0 + 8;
                float b0 = (quarter == 0) ? g_bqk[q] : 0.f;
                float b1 = (quarter == 0) ? g_bqk[q + 1] : 0.f;
                *(float2*)(g_q2p[quarter] + r0 * HH + q) = make_float2(acc[nt][0] + b0, acc[nt][1] + b1);
                *(float2*)(g_q2p[quarter] + r1 * HH + q) = make_float2(acc[nt][2] + b0, acc[nt][3] + b1);
            }
        }
        grid_sync(128);

        // ---------- Phase B: attention, 2 batches per CTA ----------
        {
            int sub = tid >> 8, stid = tid & 255;
            int sw = stid >> 5, ln = stid & 31;
            int b = cta * 2 + sub;

            float qf[16];
            {
#pragma unroll
                for (int i = 0; i < 4; ++i) {
                    float4 va = *(const float4*)(g_q2p[0] + b * HH + ln * 16 + i * 4);
                    float4 vb = *(const float4*)(g_q2p[1] + b * HH + ln * 16 + i * 4);
                    float4 vc = *(const float4*)(g_q2p[2] + b * HH + ln * 16 + i * 4);
                    float4 vd = *(const float4*)(g_q2p[3] + b * HH + ln * 16 + i * 4);
                    qf[i * 4 + 0] = va.x + vb.x + vc.x + vd.x;
                    qf[i * 4 + 1] = va.y + vb.y + vc.y + vd.y;
                    qf[i * 4 + 2] = va.z + vb.z + vc.z + vd.z;
                    qf[i * 4 + 3] = va.w + vb.w + vc.w + vd.w;
                }
            }

            float m = -INFINITY, lsum = 0.f;
            float ca[16];
#pragma unroll
            for (int q = 0; q < 16; ++q) ca[q] = 0.f;

            const __nv_bfloat16* hb0 = g_hsb + ((size_t)sw * BB + b) * HH + ln * 16;
            uint4 u0 = *(const uint4*)hb0;
            uint4 u1 = *(const uint4*)(hb0 + 8);

#pragma unroll 4
            for (int it = 0; it < SS / 8; ++it) {
                uint4 c0 = u0, c1 = u1;
                if (it + 1 < SS / 8) {
                    const __nv_bfloat16* hb = g_hsb + ((size_t)(sw + (it + 1) * 8) * BB + b) * HH + ln * 16;
                    u0 = *(const uint4*)hb;
                    u1 = *(const uint4*)(hb + 8);
                }
                float f[16];
                {
                    const __nv_bfloat162* p0 = (const __nv_bfloat162*)&c0;
                    const __nv_bfloat162* p1 = (const __nv_bfloat162*)&c1;
#pragma unroll
                    for (int j = 0; j < 4; ++j) {
                        float2 v = __bfloat1622float2(p0[j]);
                        f[2 * j] = v.x; f[2 * j + 1] = v.y;
                        float2 v2 = __bfloat1622float2(p1[j]);
                        f[8 + 2 * j] = v2.x; f[8 + 2 * j + 1] = v2.y;
                    }
                }
                float dot = 0.f;
#pragma unroll
                for (int q = 0; q < 16; ++q) dot += f[q] * qf[q];
#pragma unroll
                for (int off = 16; off; off >>= 1) dot += __shfl_xor_sync(0xffffffffu, dot, off);
                float mn = fmaxf(m, dot);
                float scl = __expf(m - mn);
                float p = __expf(dot - mn);
                m = mn;
                lsum = lsum * scl + p;
#pragma unroll
                for (int q = 0; q < 16; ++q) ca[q] = ca[q] * scl + p * f[q];
            }

            float* sc = (float*)(smem + sub * ATT_SUB);
            float* smx = (float*)(smem + sub * ATT_SUB + 16384);
            float* slx = (float*)(smem + sub * ATT_SUB + 16416);
#pragma unroll
            for (int q = 0; q < 16; ++q) sc[sw * HH + ln * 16 + q] = ca[q];
            if (ln == 0) { smx[sw] = m; slx[sw] = lsum; }
            __syncthreads();

            float M = smx[0];
#pragma unroll
            for (int w2 = 1; w2 < 8; ++w2) M = fmaxf(M, smx[w2]);
            float ew[8];
            float L = 0.f;
#pragma unroll
            for (int w2 = 0; w2 < 8; ++w2) { ew[w2] = __expf(smx[w2] - M); L += slx[w2] * ew[w2]; }
            float invL = __fdividef(1.f, L);
            {
                int h = stid * 2;
                float va = 0.f, vb = 0.f;
#pragma unroll
                for (int w2 = 0; w2 < 8; ++w2) {
                    va += ew[w2] * sc[w2 * HH + h];
                    vb += ew[w2] * sc[w2 * HH + h + 1];
                }
                va *= invL; vb *= invL;
                __nv_bfloat16 ba = __float2bfloat16(va), bb = __float2bfloat16(vb);
                __nv_bfloat162 hi2; hi2.x = ba; hi2.y = bb;
                __nv_bfloat162 lo2;
                lo2.x = __float2bfloat16(va - __bfloat162float(ba));
                lo2.y = __float2bfloat16(vb - __bfloat162float(bb));
                *(__nv_bfloat162*)&g_ctxhi[b * HH + h] = hi2;
                *(__nv_bfloat162*)&g_ctxlo[b * HH + h] = lo2;
            }
        }
        grid_sync(128);

        // ---------- Phase C: gates += ctx @ Wc^T, LSTM epilogue ----------
        {
            int n0 = (cta & 31) * 64;
            int m0 = (cta >> 5) * 64;
            float acc[2][4];
#pragma unroll
            for (int nt = 0; nt < 2; ++nt)
#pragma unroll
                for (int r = 0; r < 4; ++r) acc[nt][r] = 0.f;
            gemm_pipe(g_ctxhi + (size_t)m0 * HH, g_ctxlo + (size_t)m0 * HH,
                      g_Wc_hi + (size_t)n0 * HH, g_Wc_lo + (size_t)n0 * HH,
                      0, 8, sb, tid, mrow, ncol, rowsel, acc);

            float* Cs = (float*)smem;   // stage-0 region; disjoint from stage-3 trailing reads
            {
#pragma unroll
                for (int nt = 0; nt < 2; ++nt) {
                    int col = ncol + nt * 8 + cc * 2;
                    int r0 = mrow + g2, r1 = mrow + g2 + 8;
                    Cs[r0 * 68 + col]     = acc[nt][0];
                    Cs[r0 * 68 + col + 1] = acc[nt][1];
                    Cs[r1 * 68 + col]     = acc[nt][2];
                    Cs[r1 * 68 + col + 1] = acc[nt][3];
                }
            }
            __syncthreads();

            int bnew = tid >> 3, kp = tid & 7;
            int b = m0 + bnew;
            int hl0 = kp * 2;
            int hbase = n0 >> 2;
            int jp = n0 + kp * 8;
            float4 c0 = *(float4*)&Cs[bnew * 68 + kp * 8];
            float4 c1 = *(float4*)&Cs[bnew * 68 + kp * 8 + 4];
            float4 gr0 = *(const float4*)(g_gates + b * GG + jp);
            float4 gr1 = *(const float4*)(g_gates + b * GG + jp + 4);
            float4 bd0 = *(const float4*)(g_bd2 + jp);
            float4 bd1 = *(const float4*)(g_bd2 + jp + 4);
            int idx = b * HH + hbase + hl0;
            float2 cold = *(float2*)&g_c[idx];
            float h0, h1, cn0, cn1;
            {
                float ig = fsig(c0.x + gr0.x + bd0.x);
                float fg = fsig(c0.y + gr0.y + bd0.y);
                float gg = ftanh(c0.z + gr0.z + bd0.z);
                float og = fsig(c0.w + gr0.w + bd0.w);
                cn0 = fg * cold.x + ig * gg;
                h0 = og * ftanh(cn0);
            }
            {
                float ig = fsig(c1.x + gr1.x + bd1.x);
                float fg = fsig(c1.y + gr1.y + bd1.y);
                float gg = ftanh(c1.z + gr1.z + bd1.z);
                float og = fsig(c1.w + gr1.w + bd1.w);
                cn1 = fg * cold.y + ig * gg;
                h1 = og * ftanh(cn1);
            }
            *(float2*)&g_c[idx] = make_float2(cn0, cn1);
            *(float2*)&g_hbuf[op][idx] = make_float2(h0, h1);
            __nv_bfloat16 b0 = __float2bfloat16(h0), b1 = __float2bfloat16(h1);
            __nv_bfloat162 hi2; hi2.x = b0; hi2.y = b1;
            __nv_bfloat162 lo2;
            lo2.x = __float2bfloat16(h0 - __bfloat162float(b0));
            lo2.y = __float2bfloat16(h1 - __bfloat162float(b1));
            *(__nv_bfloat162*)&g_hhi[op][idx] = hi2;
            *(__nv_bfloat162*)&g_hlo[op][idx] = lo2;
        }
        grid_sync(128);

        // ---------- Phase D: output projection ----------
        if (w < 2) {
            int b = cta * 2 + w;
            const float* hp = g_hbuf[op] + b * HH;
            float p = 0.f;
#pragma unroll
            for (int q = 0; q < 16; ++q) p += hp[l + (q << 5)] * outW[l + (q << 5)];
#pragma unroll
            for (int off = 16; off; off >>= 1) p += __shfl_xor_sync(0xffffffffu, p, off);
            if (l == 0) out[b * TT + t] = p + outb[0];
        }
    }
}

// ================= prep (3 launches total) =================
// P1: all elementwise/local prep fused
__global__ void k_prep1(const float* __restrict__ embW, const float* __restrict__ embb,
                        const float* __restrict__ encWih, const float* __restrict__ encbih,
                        const float* __restrict__ encbhh, const float* __restrict__ encWhh,
                        const float* __restrict__ dWih, const float* __restrict__ dWhh,
                        const float* __restrict__ dbih, const float* __restrict__ dbhh) {
    int idx = blockIdx.x * 256 + threadIdx.x;   // 0 .. GG*HH-1
    {
        int jp = idx >> 9, k = idx & (HH - 1);
        int h = jp >> 2, g = jp & 3;
        // encoder Whh split
        float we = encWhh[(g * HH + h) * HH + k];
        __nv_bfloat16 hie = __float2bfloat16(we);
        g_Wenc_hi[idx] = hie;
        g_Wenc_lo[idx] = __float2bfloat16(we - __bfloat162float(hie));
        // decoder gates_h: Wih[:, :H] + Whh
        float wa = dWih[(g * HH + h) * K2 + k] + dWhh[(g * HH + h) * HH + k];
        __nv_bfloat16 hia = __float2bfloat16(wa);
        g_WA_hi[idx] = hia;
        g_WA_lo[idx] = __float2bfloat16(wa - __bfloat162float(hia));
        // decoder ctx half: Wih[:, H:]
        float wc = dWih[(g * HH + h) * K2 + HH + k];
        __nv_bfloat16 hic = __float2bfloat16(wc);
        g_Wc_hi[idx] = hic;
        g_Wc_lo[idx] = __float2bfloat16(wc - __bfloat162float(hic));
    }
    if (idx < GG) {
        int h = idx >> 2, g = idx & 3;
        int j = g * HH + h;   // original row
        float v = 0.f, u = 0.f;
        const float* wr = encWih + j * RR;
#pragma unroll 8
        for (int r = 0; r < RR; ++r) { v += embW[r] * wr[r]; u += embb[r] * wr[r]; }
        g_v2[idx] = v;
        g_u2[idx] = u + encbih[j] + encbhh[j];
        g_bd2[idx] = dbih[j] + dbhh[j];
    }
    if (idx < BB * HH) {
        g_hhi[0][idx] = __float2bfloat16(0.f);
        g_hlo[0][idx] = __float2bfloat16(0.f);
    }
}

// P2: dual 512x512 transpose (z=0: Wk->WkT, z=1: Wq->WqT)
__global__ void k_prep2(const float* __restrict__ Wk, const float* __restrict__ Wq) {
    __shared__ float t[32][33];
    const float* in = blockIdx.z ? Wq : Wk;
    float* outp = blockIdx.z ? g_WqT : g_WkT;
    int x = blockIdx.x * 32 + threadIdx.x;
    int y0 = blockIdx.y * 32;
    for (int j = threadIdx.y; j < 32; j += 8) t[j][threadIdx.x] = in[(y0 + j) * HH + x];
    __syncthreads();
    int x2 = y0 + threadIdx.x;
    int y20 = blockIdx.x * 32;
    for (int j = threadIdx.y; j < 32; j += 8) outp[(y20 + j) * HH + x2] = t[threadIdx.x][j];
}

// P3: At = WkT @ WqT^T, split directly into WA rows GG..GG+511; blocks x==0 also do bqk
__global__ __launch_bounds__(256) void k_prep3(const float* __restrict__ bq) {
    __shared__ float As[32][33];
    __shared__ float Bs[32][33];
    int tid = threadIdx.x;
    int m0 = blockIdx.y * 32, n0 = blockIdx.x * 32;
    int lr = tid >> 3, lk = (tid & 7) << 2;
    int ty = tid >> 4, tx = tid & 15;
    float acc00 = 0.f, acc01 = 0.f, acc10 = 0.f, acc11 = 0.f;
    for (int kk = 0; kk < HH; kk += 32) {
        float4 a = *(const float4*)(g_WkT + (m0 + lr) * HH + kk + lk);
        float4 b = *(const float4*)(g_WqT + (n0 + lr) * HH + kk + lk);
        __syncthreads();
        As[lk + 0][lr] = a.x; As[lk + 1][lr] = a.y; As[lk + 2][lr] = a.z; As[lk + 3][lr] = a.w;
        Bs[lk + 0][lr] = b.x; Bs[lk + 1][lr] = b.y; Bs[lk + 2][lr] = b.z; Bs[lk + 3][lr] = b.w;
        __syncthreads();
#pragma unroll
        for (int k = 0; k < 32; ++k) {
            float a0 = As[k][ty * 2], a1 = As[k][ty * 2 + 1];
            float b0 = Bs[k][tx * 2], b1 = Bs[k][tx * 2 + 1];
            acc00 += a0 * b0; acc01 += a0 * b1;
            acc10 += a1 * b0; acc11 += a1 * b1;
        }
    }
    // write split directly into WA rows (GG + m), col p
    auto wr = [&](int m, int p, float v) {
        size_t d = (size_t)(GG + m) * HH + p;
        __nv_bfloat16 hi = __float2bfloat16(v);
        g_WA_hi[d] = hi;
        g_WA_lo[d] = __float2bfloat16(v - __bfloat162float(hi));
    };
    wr(m0 + ty * 2 + 0, n0 + tx * 2 + 0, acc00);
    wr(m0 + ty * 2 + 0, n0 + tx * 2 + 1, acc01);
    wr(m0 + ty * 2 + 1, n0 + tx * 2 + 0, acc10);
    wr(m0 + ty * 2 + 1, n0 + tx * 2 + 1, acc11);

    // bqk for this m-range (blocks with n0==0 only)
    if (blockIdx.x == 0) {
        int wv = tid >> 5, ln = tid & 31;
#pragma unroll
        for (int it = 0; it < 4; ++it) {
            int m = m0 + wv + it * 8;
            const float* row = g_WkT + (size_t)m * HH;
            float a = 0.f;
            for (int n = ln; n < HH; n += 32) a += bq[n] * row[n];
#pragma unroll
            for (int off = 16; off; off >>= 1) a += __shfl_xor_sync(0xffffffffu, a, off);
            if (ln == 0) g_bqk[m] = a;
        }
    }
}

// ---------------- host launcher ----------------
extern "C" void kernel_launch(void* const* d_in, const int* in_sizes, int n_in,
                              void* d_out, int out_size) {
    int off = (n_in >= 18 && in_sizes[1] == 1) ? 1 : 0;
    const float* enc_inputs = (const float*)d_in[0];
    const float* embed_W = (const float*)d_in[1 + off];
    const float* embed_b = (const float*)d_in[2 + off];
    const float* enc_Wih = (const float*)d_in[3 + off];
    const float* enc_Whh = (const float*)d_in[4 + off];
    const float* enc_bih = (const float*)d_in[5 + off];
    const float* enc_bhh = (const float*)d_in[6 + off];
    const float* dec_Wih = (const float*)d_in[7 + off];
    const float* dec_Whh = (const float*)d_in[8 + off];
    const float* dec_bih = (const float*)d_in[9 + off];
    const float* dec_bhh = (const float*)d_in[10 + off];
    const float* Wq = (const float*)d_in[11 + off];
    const float* bq = (const float*)d_in[12 + off];
    const float* Wk = (const float*)d_in[13 + off];
    // bk dropped: uniform over s -> softmax-invariant
    const float* out_W = (const float*)d_in[15 + off];
    const float* out_b = (const float*)d_in[16 + off];
    float* out = (float*)d_out;

    cudaFuncSetAttribute(lstm_enc_persist, cudaFuncAttributeMaxDynamicSharedMemorySize, PSMEM);
    cudaFuncSetAttribute(dec_persist, cudaFuncAttributeMaxDynamicSharedMemorySize, SMEM_DEC);

    // ---- prep: exactly 3 launches ----
    k_prep1<<<(GG * HH) / 256, 256>>>(embed_W, embed_b, enc_Wih, enc_bih, enc_bhh,
                                      enc_Whh, dec_Wih, dec_Whh, dec_bih, dec_bhh);
    dim3 tb(32, 8);
    k_prep2<<<dim3(16, 16, 2), tb>>>(Wk, Wq);
    k_prep3<<<dim3(16, 16), 256>>>(bq);

    // ---- encoder: ONE persistent kernel (4th launch -> ncu-visible) ----
    lstm_enc_persist<<<dim3(32, 4), 512, PSMEM>>>(enc_inputs);

    // ---- decoder: ONE persistent kernel ----
    dec_persist<<<128, 512, SMEM_DEC>>>(out_W, out_b, out);

    (void)in_sizes; (void)n_in; (void)out_size;
}